// round 13
// baseline (speedup 1.0000x reference)
#include <cuda_runtime.h>
#include <cuda_fp16.h>
#include <cstdint>

// ---------------------------------------------------------------------------
// ModalityRouter via mma.sync m16n8k16.f16, 2-limb fp32 split (3 products).
// 1024 uniform CTAs x 32 tokens, 128 threads, 4 warps (M16xN32, one/SMSP),
// 7 CTAs/SM. A+B staged via 4-slot cp.async pipeline, PAIR-committed:
// one wait_group + one __syncthreads per 32 k-columns (half of R12's sync).
//   x: [32768, 2048] fp32   gate_w: [64, 2048] fp32
// Output fp32: gates[65536] | idx[65536] | load[64] | top_logits[65536]
// ---------------------------------------------------------------------------

#define DK        2048
#define NE        64
#define NTOK      32768
#define BM        32
#define NCTA      (NTOK / BM)     // 1024
#define NTHREADS  128
#define NGROUPS   (DK / 16)       // 128 k-groups of 16
#define NPAIRS    (NGROUPS / 2)   // 64
#define STAGE_BYTES 6144          // A 2KB + B 4KB
#define SMEM_DYN  (4 * STAGE_BYTES)   // 24576

// fragment-major fp16 limb split of gate_w (layout identical to R12):
//   g_Bfrag[es*NGROUPS*128 + g*128 + nt*32 + lane] = {hi.x, hi.y, lo.x, lo.y}
__device__ uint4 g_Bfrag[2 * NGROUPS * 4 * 32];     // 512 KB

__device__ __forceinline__ uint32_t pack_h2(float a, float b) {
    __half2 h = __halves2half2(__float2half_rn(a), __float2half_rn(b));
    return *reinterpret_cast<uint32_t*>(&h);
}

__global__ void prep_kernel(const float* __restrict__ w, float* __restrict__ out_load) {
    const int t = blockIdx.x * 128 + threadIdx.x;    // 32768 threads total
    if (blockIdx.x == 0 && threadIdx.x < NE) out_load[threadIdx.x] = 0.0f;

    const int lane = t & 31;
    const int nt   = (t >> 5) & 3;
    const int g    = (t >> 7) & (NGROUPS - 1);
    const int es   = t >> 14;
    const int gid  = lane >> 2;
    const int tig  = lane & 3;
    const int e    = es * 32 + nt * 8 + gid;
    const int kb   = g * 16 + tig * 4;

    float4 v = *reinterpret_cast<const float4*>(w + (size_t)e * DK + kb);
    float hx = __half2float(__float2half_rn(v.x));
    float hy = __half2float(__float2half_rn(v.y));
    float hz = __half2float(__float2half_rn(v.z));
    float hw = __half2float(__float2half_rn(v.w));

    uint4 frag;
    frag.x = pack_h2(v.x, v.y);                 // hi limb
    frag.y = pack_h2(v.z, v.w);
    frag.z = pack_h2(v.x - hx, v.y - hy);       // lo limb
    frag.w = pack_h2(v.z - hz, v.w - hw);
    g_Bfrag[t] = frag;
}

// warp-level tensor op: D += A(f16) * B(f16), f32 accumulate
__device__ __forceinline__ void mma16(float* d, const uint32_t* a,
                                      uint32_t b0, uint32_t b1) {
    asm volatile(
        "mma.sync.aligned.m16n8k16.row.col.f32.f16.f16.f32 "
        "{%0,%1,%2,%3}, {%4,%5,%6,%7}, {%8,%9}, {%0,%1,%2,%3};"
        : "+f"(d[0]), "+f"(d[1]), "+f"(d[2]), "+f"(d[3])
        : "r"(a[0]), "r"(a[1]), "r"(a[2]), "r"(a[3]), "r"(b0), "r"(b1));
}

// split a float2 into (hi half2, lo half2)
__device__ __forceinline__ void split2(float2 f, uint32_t& hi, uint32_t& lo) {
    __half2 h = __float22half2_rn(f);
    float2 hf = __half22float2(h);
    __half2 l = __float22half2_rn(make_float2(f.x - hf.x, f.y - hf.y));
    hi = *reinterpret_cast<uint32_t*>(&h);
    lo = *reinterpret_cast<uint32_t*>(&l);
}

__device__ __forceinline__ void cp_async16(uint32_t saddr, const void* gaddr) {
    asm volatile("cp.async.cg.shared.global [%0], [%1], 16;"
                 :: "r"(saddr), "l"(gaddr));
}
#define CP_COMMIT()  asm volatile("cp.async.commit_group;" ::: "memory")
#define CP_WAIT(n)   asm volatile("cp.async.wait_group %0;" :: "n"(n) : "memory")

// ---------------------------------------------------------------------------
__global__ void __launch_bounds__(NTHREADS, 7)
router_kernel(const float* __restrict__ x, float* __restrict__ out)
{
    extern __shared__ __align__(16) unsigned char dyn[];   // stages / logits
    __shared__ float sg[2 * BM];
    __shared__ int   si[2 * BM];

    const int tid    = threadIdx.x;
    const int wid    = tid >> 5;
    const int lane   = tid & 31;
    const int gid    = lane >> 2;       // fragment row/col group (0..7)
    const int tig    = lane & 3;        // thread-in-group (0..3)
    const int tslice = wid >> 1;        // token slice (0..1): 16 tokens each
    const int eslice = wid & 1;         // expert slice (0..1): 32 experts each
    const int tok0   = blockIdx.x * BM;

    // ---- loader coordinates (identical mapping to R12) ----
    const float* xg = x + (size_t)(tok0 + (tid >> 2)) * DK + (tid & 3) * 4;
    const uint32_t a_slot = (uint32_t)tid * 16;
    const uint4* bsrc0 = g_Bfrag + tid;                              // es0
    const uint4* bsrc1 = g_Bfrag + (size_t)NGROUPS * 128 + tid;      // es1
    const uint32_t b_slot0 = 2048 + (uint32_t)tid * 16;
    const uint32_t b_slot1 = 4096 + (uint32_t)tid * 16;
    const uint32_t sbase = (uint32_t)__cvta_generic_to_shared(dyn);

    float acc[4][4];
#pragma unroll
    for (int nt = 0; nt < 4; nt++)
#pragma unroll
        for (int q = 0; q < 4; q++) acc[nt][q] = 0.0f;

    // ---- prologue: issue stages 0,1 as ONE commit group ----
#pragma unroll
    for (int g = 0; g < 2; g++) {
        const uint32_t sb = sbase + (g & 3) * STAGE_BYTES;
        cp_async16(sb + a_slot,  xg + g * 16);
        cp_async16(sb + b_slot0, bsrc0 + (size_t)g * 128);
        cp_async16(sb + b_slot1, bsrc1 + (size_t)g * 128);
    }
    CP_COMMIT();

    for (int p = 0; p < NPAIRS; ++p) {
        // pair p's stages (2p, 2p+1) landed; publish to all warps
        CP_WAIT(0);
        __syncthreads();

        // issue pair p+1 (stages 2p+2, 2p+3) into the slots freed at pair p-1
        if (p + 1 < NPAIRS) {
#pragma unroll
            for (int s = 0; s < 2; s++) {
                const int gp = 2 * p + 2 + s;
                const uint32_t sb = sbase + (gp & 3) * STAGE_BYTES;
                cp_async16(sb + a_slot,  xg + gp * 16);
                cp_async16(sb + b_slot0, bsrc0 + (size_t)gp * 128);
                cp_async16(sb + b_slot1, bsrc1 + (size_t)gp * 128);
            }
            CP_COMMIT();
        }

        // ---- consume both stages of the pair ----
#pragma unroll
        for (int s = 0; s < 2; s++) {
            const int g = 2 * p + s;
            const unsigned char* stg = dyn + (g & 3) * STAGE_BYTES;
            const float4* as = reinterpret_cast<const float4*>(stg);
            const uint4*  bs = reinterpret_cast<const uint4*>(stg + 2048)
                               + eslice * 128 + lane;

            // A fragments (2 x LDS.128, warp-contiguous) + limb split
            float4 v0 = as[(tslice * 16 + gid) * 4 + tig];
            float4 v1 = as[(tslice * 16 + 8 + gid) * 4 + tig];
            uint32_t ah[4], al[4];
            split2(make_float2(v0.x, v0.y), ah[0], al[0]);
            split2(make_float2(v1.x, v1.y), ah[1], al[1]);
            split2(make_float2(v0.z, v0.w), ah[2], al[2]);
            split2(make_float2(v1.z, v1.w), ah[3], al[3]);

            // B fragments (4 x LDS.128, warp-contiguous)
            uint4 b0 = bs[0 * 32];
            uint4 b1 = bs[1 * 32];
            uint4 b2 = bs[2 * 32];
            uint4 b3 = bs[3 * 32];

            // 12 MMAs, product-major (per-acc order identical to R12)
            mma16(acc[0], ah, b0.x, b0.y);   // hi*hi
            mma16(acc[1], ah, b1.x, b1.y);
            mma16(acc[2], ah, b2.x, b2.y);
            mma16(acc[3], ah, b3.x, b3.y);
            mma16(acc[0], ah, b0.z, b0.w);   // hi*lo
            mma16(acc[1], ah, b1.z, b1.w);
            mma16(acc[2], ah, b2.z, b2.w);
            mma16(acc[3], ah, b3.z, b3.w);
            mma16(acc[0], al, b0.x, b0.y);   // lo*hi
            mma16(acc[1], al, b1.x, b1.y);
            mma16(acc[2], al, b2.x, b2.y);
            mma16(acc[3], al, b3.x, b3.y);
        }
    }

    __syncthreads();                       // all reads of dyn done; repurpose

    float (*lg)[NE + 1] = reinterpret_cast<float(*)[NE + 1]>(dyn);
#pragma unroll
    for (int nt = 0; nt < 4; nt++) {
        const int r = tslice * 16 + gid;
        const int e = eslice * 32 + nt * 8 + 2 * tig;
        lg[r][e]         = acc[nt][0];
        lg[r][e + 1]     = acc[nt][1];
        lg[r + 8][e]     = acc[nt][2];
        lg[r + 8][e + 1] = acc[nt][3];
    }
    __syncthreads();

    float* out_gates = out;
    float* out_idx   = out + 2 * NTOK;
    float* out_load  = out + 4 * NTOK;
    float* out_tlog  = out + 4 * NTOK + NE;

    if (tid < BM) {
        const float* row = lg[tid];
        // jax.lax.top_k tie-break: lowest index wins -> strict '>' ascending scan
        float m1 = -1e30f, m2 = -1e30f;
        int   i1 = 0,      i2 = 0;
#pragma unroll 8
        for (int e = 0; e < NE; e++) {
            float v = row[e];
            if (v > m1)      { m2 = m1; i2 = i1; m1 = v; i1 = e; }
            else if (v > m2) { m2 = v;  i2 = e; }
        }
        float ex  = expf(m2 - m1);      // stable: m1 >= m2
        float inv = 1.0f / (1.0f + ex);
        float g1  = inv;
        float g2  = ex * inv;

        const int t = tok0 + tid;
        reinterpret_cast<float2*>(out_gates)[t] = make_float2(g1, g2);
        reinterpret_cast<float2*>(out_idx)[t]   = make_float2((float)i1, (float)i2);
        reinterpret_cast<float2*>(out_tlog)[t]  = make_float2(m1, m2);

        sg[2 * tid] = g1;  sg[2 * tid + 1] = g2;
        si[2 * tid] = i1;  si[2 * tid + 1] = i2;
    }
    __syncthreads();

    // per-CTA deterministic expert-load partial, one atomic per expert per CTA
    if (tid < NE) {
        float ssum = 0.0f;
#pragma unroll 8
        for (int n = 0; n < 2 * BM; n++)
            ssum += (si[n] == tid) ? sg[n] : 0.0f;
        atomicAdd(out_load + tid, ssum);
    }
}

// ---------------------------------------------------------------------------
extern "C" void kernel_launch(void* const* d_in, const int* in_sizes, int n_in,
                              void* d_out, int out_size) {
    const float* x = (const float*)d_in[0];   // [32768, 2048]
    const float* w = (const float*)d_in[1];   // [64, 2048]
    float* out = (float*)d_out;

    cudaFuncSetAttribute(router_kernel,
                         cudaFuncAttributeMaxDynamicSharedMemorySize, SMEM_DYN);

    prep_kernel<<<256, 128>>>(w, out + 4 * NTOK);      // frag-major B limbs + zero load
    router_kernel<<<NCTA, NTHREADS, SMEM_DYN>>>(x, out);
}

// round 14
// speedup vs baseline: 1.1744x; 1.1744x over previous
#include <cuda_runtime.h>
#include <cuda_fp16.h>
#include <cstdint>

// ---------------------------------------------------------------------------
// ModalityRouter via mma.sync m16n8k16.f16, 2-limb fp32 split (3 products).
// R12 configuration (best measured): 1024 uniform CTAs x 32 tokens, 128
// threads, 4 warps (M16xN32, one per SMSP), 7 CTAs/SM, 4-slot cp.async
// pipeline with wait_group(2). Deltas vs R12: prep grid 256x128, unroll 4.
//   x: [32768, 2048] fp32   gate_w: [64, 2048] fp32
// Output fp32: gates[65536] | idx[65536] | load[64] | top_logits[65536]
// ---------------------------------------------------------------------------

#define DK        2048
#define NE        64
#define NTOK      32768
#define BM        32
#define NCTA      (NTOK / BM)     // 1024
#define NTHREADS  128
#define NGROUPS   (DK / 16)       // 128 k-groups of 16
#define NSTAGE    4
#define STAGE_BYTES 6144          // A 2KB + B 4KB
#define SMEM_DYN  (NSTAGE * STAGE_BYTES)   // 24576

// fragment-major fp16 limb split of gate_w (layout identical to R12):
//   g_Bfrag[es*NGROUPS*128 + g*128 + nt*32 + lane] = {hi.x, hi.y, lo.x, lo.y}
__device__ uint4 g_Bfrag[2 * NGROUPS * 4 * 32];     // 512 KB

__device__ __forceinline__ uint32_t pack_h2(float a, float b) {
    __half2 h = __halves2half2(__float2half_rn(a), __float2half_rn(b));
    return *reinterpret_cast<uint32_t*>(&h);
}

__global__ void prep_kernel(const float* __restrict__ w, float* __restrict__ out_load) {
    const int t = blockIdx.x * 128 + threadIdx.x;    // 32768 threads total
    if (blockIdx.x == 0 && threadIdx.x < NE) out_load[threadIdx.x] = 0.0f;

    const int lane = t & 31;
    const int nt   = (t >> 5) & 3;
    const int g    = (t >> 7) & (NGROUPS - 1);
    const int es   = t >> 14;
    const int gid  = lane >> 2;
    const int tig  = lane & 3;
    const int e    = es * 32 + nt * 8 + gid;
    const int kb   = g * 16 + tig * 4;

    float4 v = *reinterpret_cast<const float4*>(w + (size_t)e * DK + kb);
    float hx = __half2float(__float2half_rn(v.x));
    float hy = __half2float(__float2half_rn(v.y));
    float hz = __half2float(__float2half_rn(v.z));
    float hw = __half2float(__float2half_rn(v.w));

    uint4 frag;
    frag.x = pack_h2(v.x, v.y);                 // hi limb
    frag.y = pack_h2(v.z, v.w);
    frag.z = pack_h2(v.x - hx, v.y - hy);       // lo limb
    frag.w = pack_h2(v.z - hz, v.w - hw);
    g_Bfrag[t] = frag;
}

// warp-level tensor op: D += A(f16) * B(f16), f32 accumulate
__device__ __forceinline__ void mma16(float* d, const uint32_t* a,
                                      uint32_t b0, uint32_t b1) {
    asm volatile(
        "mma.sync.aligned.m16n8k16.row.col.f32.f16.f16.f32 "
        "{%0,%1,%2,%3}, {%4,%5,%6,%7}, {%8,%9}, {%0,%1,%2,%3};"
        : "+f"(d[0]), "+f"(d[1]), "+f"(d[2]), "+f"(d[3])
        : "r"(a[0]), "r"(a[1]), "r"(a[2]), "r"(a[3]), "r"(b0), "r"(b1));
}

// split a float2 into (hi half2, lo half2)
__device__ __forceinline__ void split2(float2 f, uint32_t& hi, uint32_t& lo) {
    __half2 h = __float22half2_rn(f);
    float2 hf = __half22float2(h);
    __half2 l = __float22half2_rn(make_float2(f.x - hf.x, f.y - hf.y));
    hi = *reinterpret_cast<uint32_t*>(&h);
    lo = *reinterpret_cast<uint32_t*>(&l);
}

__device__ __forceinline__ void cp_async16(uint32_t saddr, const void* gaddr) {
    asm volatile("cp.async.cg.shared.global [%0], [%1], 16;"
                 :: "r"(saddr), "l"(gaddr));
}
#define CP_COMMIT()  asm volatile("cp.async.commit_group;" ::: "memory")
#define CP_WAIT(n)   asm volatile("cp.async.wait_group %0;" :: "n"(n) : "memory")

// ---------------------------------------------------------------------------
__global__ void __launch_bounds__(NTHREADS, 7)
router_kernel(const float* __restrict__ x, float* __restrict__ out)
{
    extern __shared__ __align__(16) unsigned char dyn[];   // stages / logits
    __shared__ float sg[2 * BM];
    __shared__ int   si[2 * BM];

    const int tid    = threadIdx.x;
    const int wid    = tid >> 5;
    const int lane   = tid & 31;
    const int gid    = lane >> 2;       // fragment row/col group (0..7)
    const int tig    = lane & 3;        // thread-in-group (0..3)
    const int tslice = wid >> 1;        // token slice (0..1): 16 tokens each
    const int eslice = wid & 1;         // expert slice (0..1): 32 experts each
    const int tok0   = blockIdx.x * BM;

    // ---- loader coordinates ----
    // A: 128 threads x 16B = 2KB/group. token = tid>>2, k-chunk = tid&3.
    const float* xg = x + (size_t)(tok0 + (tid >> 2)) * DK + (tid & 3) * 4;
    const uint32_t a_slot = (uint32_t)tid * 16;
    // B: 4KB/group (es0 then es1), 2 x 16B per thread
    const uint4* bsrc0 = g_Bfrag + tid;                              // es0
    const uint4* bsrc1 = g_Bfrag + (size_t)NGROUPS * 128 + tid;      // es1
    const uint32_t b_slot0 = 2048 + (uint32_t)tid * 16;
    const uint32_t b_slot1 = 4096 + (uint32_t)tid * 16;
    const uint32_t sbase = (uint32_t)__cvta_generic_to_shared(dyn);

    float acc[4][4];
#pragma unroll
    for (int nt = 0; nt < 4; nt++)
#pragma unroll
        for (int q = 0; q < 4; q++) acc[nt][q] = 0.0f;

    // ---- prologue: issue stages 0..2 ----
#pragma unroll
    for (int g = 0; g < NSTAGE - 1; g++) {
        const uint32_t sb = sbase + (g & 3) * STAGE_BYTES;
        cp_async16(sb + a_slot,  xg + g * 16);
        cp_async16(sb + b_slot0, bsrc0 + (size_t)g * 128);
        cp_async16(sb + b_slot1, bsrc1 + (size_t)g * 128);
        CP_COMMIT();
    }

#pragma unroll 4
    for (int g = 0; g < NGROUPS; ++g) {
        // stage g complete; make visible to all warps
        CP_WAIT(2);
        __syncthreads();

        // issue stage g+3 into the slot freed by the barrier
        if (g + 3 < NGROUPS) {
            const int gp = g + 3;
            const uint32_t sb = sbase + (gp & 3) * STAGE_BYTES;
            cp_async16(sb + a_slot,  xg + gp * 16);
            cp_async16(sb + b_slot0, bsrc0 + (size_t)gp * 128);
            cp_async16(sb + b_slot1, bsrc1 + (size_t)gp * 128);
        }
        CP_COMMIT();                       // commit every group (empty ok)

        const unsigned char* stg = dyn + (g & 3) * STAGE_BYTES;
        const float4* as = reinterpret_cast<const float4*>(stg);
        const uint4*  bs = reinterpret_cast<const uint4*>(stg + 2048) + eslice * 128 + lane;

        // ---- A fragments (2 x LDS.128, warp-contiguous) + limb split ----
        float4 v0 = as[(tslice * 16 + gid) * 4 + tig];
        float4 v1 = as[(tslice * 16 + 8 + gid) * 4 + tig];
        uint32_t ah[4], al[4];
        split2(make_float2(v0.x, v0.y), ah[0], al[0]);
        split2(make_float2(v1.x, v1.y), ah[1], al[1]);
        split2(make_float2(v0.z, v0.w), ah[2], al[2]);
        split2(make_float2(v1.z, v1.w), ah[3], al[3]);

        // ---- B fragments (4 x LDS.128, warp-contiguous) ----
        uint4 b0 = bs[0 * 32];
        uint4 b1 = bs[1 * 32];
        uint4 b2 = bs[2 * 32];
        uint4 b3 = bs[3 * 32];

        // ---- 12 MMAs, product-major (per-acc order identical to R12) ----
        mma16(acc[0], ah, b0.x, b0.y);   // hi*hi
        mma16(acc[1], ah, b1.x, b1.y);
        mma16(acc[2], ah, b2.x, b2.y);
        mma16(acc[3], ah, b3.x, b3.y);
        mma16(acc[0], ah, b0.z, b0.w);   // hi*lo
        mma16(acc[1], ah, b1.z, b1.w);
        mma16(acc[2], ah, b2.z, b2.w);
        mma16(acc[3], ah, b3.z, b3.w);
        mma16(acc[0], al, b0.x, b0.y);   // lo*hi
        mma16(acc[1], al, b1.x, b1.y);
        mma16(acc[2], al, b2.x, b2.y);
        mma16(acc[3], al, b3.x, b3.y);
    }

    // drain remaining (empty) cp.async groups, then repurpose dyn as logits
    CP_WAIT(0);
    __syncthreads();

    float (*lg)[NE + 1] = reinterpret_cast<float(*)[NE + 1]>(dyn);
#pragma unroll
    for (int nt = 0; nt < 4; nt++) {
        const int r = tslice * 16 + gid;
        const int e = eslice * 32 + nt * 8 + 2 * tig;
        lg[r][e]         = acc[nt][0];
        lg[r][e + 1]     = acc[nt][1];
        lg[r + 8][e]     = acc[nt][2];
        lg[r + 8][e + 1] = acc[nt][3];
    }
    __syncthreads();

    float* out_gates = out;
    float* out_idx   = out + 2 * NTOK;
    float* out_load  = out + 4 * NTOK;
    float* out_tlog  = out + 4 * NTOK + NE;

    if (tid < BM) {
        const float* row = lg[tid];
        // jax.lax.top_k tie-break: lowest index wins -> strict '>' ascending scan
        float m1 = -1e30f, m2 = -1e30f;
        int   i1 = 0,      i2 = 0;
#pragma unroll 8
        for (int e = 0; e < NE; e++) {
            float v = row[e];
            if (v > m1)      { m2 = m1; i2 = i1; m1 = v; i1 = e; }
            else if (v > m2) { m2 = v;  i2 = e; }
        }
        float ex  = expf(m2 - m1);      // stable: m1 >= m2
        float inv = 1.0f / (1.0f + ex);
        float g1  = inv;
        float g2  = ex * inv;

        const int t = tok0 + tid;
        reinterpret_cast<float2*>(out_gates)[t] = make_float2(g1, g2);
        reinterpret_cast<float2*>(out_idx)[t]   = make_float2((float)i1, (float)i2);
        reinterpret_cast<float2*>(out_tlog)[t]  = make_float2(m1, m2);

        sg[2 * tid] = g1;  sg[2 * tid + 1] = g2;
        si[2 * tid] = i1;  si[2 * tid + 1] = i2;
    }
    __syncthreads();

    // per-CTA deterministic expert-load partial, one atomic per expert per CTA
    if (tid < NE) {
        float ssum = 0.0f;
#pragma unroll 8
        for (int n = 0; n < 2 * BM; n++)
            ssum += (si[n] == tid) ? sg[n] : 0.0f;
        atomicAdd(out_load + tid, ssum);
    }
}

// ---------------------------------------------------------------------------
extern "C" void kernel_launch(void* const* d_in, const int* in_sizes, int n_in,
                              void* d_out, int out_size) {
    const float* x = (const float*)d_in[0];   // [32768, 2048]
    const float* w = (const float*)d_in[1];   // [64, 2048]
    float* out = (float*)d_out;

    cudaFuncSetAttribute(router_kernel,
                         cudaFuncAttributeMaxDynamicSharedMemorySize, SMEM_DYN);

    prep_kernel<<<256, 128>>>(w, out + 4 * NTOK);      // frag-major B limbs + zero load
    router_kernel<<<NCTA, NTHREADS, SMEM_DYN>>>(x, out);
}